// round 5
// baseline (speedup 1.0000x reference)
#include <cuda_runtime.h>
#include <cstdint>

typedef unsigned long long u64;

#define HW 65536           // 256*256
#define NB 8
#define NC 32
#define NBC 256

__device__ __align__(16) float g_feat[NB * NC * HW];
__device__ float g_pp[NBC * 4 * 25];
__device__ float g_filt[NBC * 25];

__device__ __forceinline__ u64 fma2(u64 a, u64 b, u64 c) {
    u64 d;
    asm("fma.rn.f32x2 %0, %1, %2, %3;" : "=l"(d) : "l"(a), "l"(b), "l"(c));
    return d;
}
__device__ __forceinline__ u64 dup(float f) {
    unsigned u = __float_as_uint(f);
    return ((u64)u << 32) | (u64)u;
}
__device__ __forceinline__ u64 pack(unsigned lo, unsigned hi) {
    u64 d;
    asm("mov.b64 %0, {%1, %2};" : "=l"(d) : "r"(lo), "r"(hi));
    return d;
}
__device__ __forceinline__ u64 packf(float lo, float hi) {
    return pack(__float_as_uint(lo), __float_as_uint(hi));
}

// ---------------------------------------------------------------------------
// Kernel 1: channel mix (1x1 conv). No x staging: coalesced LDG.128 straight
// from gmem. Thread = 4 pixel-pairs x 8 out-channels (32 u64 accs).
// Per i-step: 2 LDG.128 + 4 LDS.128 (weights, broadcast) + 32 fma2.
// grid = (128, 8), block = 256
// ---------------------------------------------------------------------------
__global__ __launch_bounds__(256, 2) void mix_kernel(
    const float* __restrict__ x,
    const float* __restrict__ w,
    const float* __restrict__ bias)
{
    __shared__ u64 wq[32 * 32];     // [i][o] duplicated, transposed
    __shared__ u64 b2[32];

    int tid = threadIdx.x;
    for (int idx = tid; idx < 1024; idx += 256) {
        int i = idx >> 5, o = idx & 31;
        wq[i * 32 + o] = dup(w[o * 32 + i]);
    }
    if (tid < 32)
        b2[tid] = dup(bias[tid]);
    __syncthreads();

    int og = tid & 3;          // out channels og*8 .. og*8+7
    int pg = tid >> 2;         // pixel-quad position 0..63

    u64 acc[32];               // acc[p*8+k]
#pragma unroll
    for (int k = 0; k < 8; k++) {
        u64 bv = b2[og * 8 + k];
#pragma unroll
        for (int p = 0; p < 4; p++) acc[p * 8 + k] = bv;
    }

    int b = blockIdx.y;
    const float4* xb = (const float4*)(x + (size_t)b * (NC * HW)
                                       + blockIdx.x * 512) + pg * 2;

#pragma unroll 4
    for (int i = 0; i < 32; i++) {
        float4 xa = xb[(size_t)i * (HW / 4)];
        float4 xc = xb[(size_t)i * (HW / 4) + 1];
        u64 xv[4] = {packf(xa.x, xa.y), packf(xa.z, xa.w),
                     packf(xc.x, xc.y), packf(xc.z, xc.w)};
        const ulonglong2* wrow = (const ulonglong2*)(wq + i * 32 + og * 8);
        ulonglong2 wA = wrow[0], wB = wrow[1], wC = wrow[2], wD = wrow[3];
        u64 wv[8] = {wA.x, wA.y, wB.x, wB.y, wC.x, wC.y, wD.x, wD.y};
#pragma unroll
        for (int p = 0; p < 4; p++)
#pragma unroll
            for (int k = 0; k < 8; k++)
                acc[p * 8 + k] = fma2(wv[k], xv[p], acc[p * 8 + k]);
    }

    u64* fb = (u64*)g_feat + (size_t)b * (NC * (HW / 2))
            + blockIdx.x * 256 + pg * 4;
#pragma unroll
    for (int k = 0; k < 8; k++) {
        u64* cp = fb + (size_t)(og * 8 + k) * (HW / 2);
        *(ulonglong2*)cp       = make_ulonglong2(acc[0 * 8 + k], acc[1 * 8 + k]);
        *((ulonglong2*)cp + 1) = make_ulonglong2(acc[2 * 8 + k], acc[3 * 8 + k]);
    }
}

// ---------------------------------------------------------------------------
// Kernel 2: adaptive pool partials on x (pooling commutes with the 1x1 conv).
// Row bins [0,52)[51,103)[102,154)[153,205)[204,256) (overlapping).
// grid = (256, 4 row-chunks), block = 256 (thread = column)
// ---------------------------------------------------------------------------
__global__ __launch_bounds__(256) void pool_kernel(const float* __restrict__ x)
{
    __shared__ float pool[25];
    int bc = blockIdx.x;
    int q  = blockIdx.y;
    int w  = threadIdx.x;
    if (w < 25) pool[w] = 0.0f;
    __syncthreads();

    const float* img = x + (size_t)bc * HW + (size_t)q * 64 * 256;

    float cs[5] = {0.f, 0.f, 0.f, 0.f, 0.f};
#pragma unroll
    for (int r = 0; r < 64; r++) {
        int h = q * 64 + r;
        float v = img[r * 256 + w];
        if (h < 52)              cs[0] += v;
        if (h >= 51 && h < 103)  cs[1] += v;
        if (h >= 102 && h < 154) cs[2] += v;
        if (h >= 153 && h < 205) cs[3] += v;
        if (h >= 204)            cs[4] += v;
    }

#pragma unroll
    for (int l = 0; l < 5; l++) {
        int s = (l * 256) / 5;
        int e = ((l + 1) * 256 + 4) / 5;
        if (w >= s && w < e) {
#pragma unroll
            for (int k = 0; k < 5; k++)
                if (cs[k] != 0.0f)
                    atomicAdd(&pool[k * 5 + l], cs[k]);
        }
    }
    __syncthreads();
    if (w < 25)
        g_pp[(bc * 4 + q) * 25 + w] = pool[w];
}

// ---------------------------------------------------------------------------
// Kernel 3: filt[b,o,kl] = bias[o] + sum_i w[o,i] * px[b,i,kl]
// grid = 8, block = 800
// ---------------------------------------------------------------------------
__global__ void filt_kernel(const float* __restrict__ w,
                            const float* __restrict__ bias)
{
    __shared__ float spx[800];
    int b = blockIdx.x;
    int t = threadIdx.x;
    int i  = t / 25;
    int kl = t - i * 25;

    float s = 0.0f;
#pragma unroll
    for (int q = 0; q < 4; q++)
        s += g_pp[((b * 32 + i) * 4 + q) * 25 + kl];
    spx[t] = s * (1.0f / 2704.0f);
    __syncthreads();

    float acc = bias[i];
#pragma unroll
    for (int ic = 0; ic < 32; ic++)
        acc += w[i * 32 + ic] * spx[ic * 25 + kl];
    g_filt[b * 800 + t] = acc;
}

// ---------------------------------------------------------------------------
// Kernel 4: depthwise 5x5 conv, r-outer register sliding window.
// Thread = 2w x 8h patch. Each input row loaded ONCE (3 LDS.64 + 2 packs)
// and scattered to all valid (ky, j) pairs: 36 LDS + 200 fma2 per thread
// (was 200 LDS). Full filter lives in 50 regs; no launch_bounds reg cap
// below ~128 so nothing spills.
// grid = (16, 256), block = 256, smem = 18.7 KB
// ---------------------------------------------------------------------------
__global__ __launch_bounds__(256, 2) void conv_kernel(float* __restrict__ out)
{
    __shared__ float sh[68 * 68];
    __shared__ u64 sf2[25];

    int bc  = blockIdx.y;
    int tx0 = (blockIdx.x & 3) * 64;
    int ty0 = (blockIdx.x >> 2) * 64;

    if (threadIdx.x < 25)
        sf2[threadIdx.x] = dup(g_filt[bc * 25 + threadIdx.x]);

    const float* img = g_feat + (size_t)bc * HW;
    for (int idx = threadIdx.x; idx < 68 * 68; idx += 256) {
        int r = idx / 68;
        int c = idx - r * 68;
        int gy = ty0 + r - 2;
        int gx = tx0 + c - 2;
        float v = 0.0f;
        if ((unsigned)gy < 256u && (unsigned)gx < 256u)
            v = img[gy * 256 + gx];
        sh[idx] = v;
    }
    __syncthreads();

    u64 f[25];
#pragma unroll
    for (int t = 0; t < 25; t++) f[t] = sf2[t];

    int x  = (threadIdx.x & 31) * 2;    // output col pair (conflict-free LDS)
    int oy = (threadIdx.x >> 5) * 8;    // first output row

    u64 acc[8];
#pragma unroll
    for (int j = 0; j < 8; j++) acc[j] = 0ull;

#pragma unroll
    for (int r = 0; r < 12; r++) {
        const float* row = sh + (oy + r) * 68 + x;
        u64 q0 = *(const u64*)(row);
        u64 q2 = *(const u64*)(row + 2);
        u64 q4 = *(const u64*)(row + 4);
        u64 p1 = pack((unsigned)(q0 >> 32), (unsigned)q2);
        u64 p3 = pack((unsigned)(q2 >> 32), (unsigned)q4);
#pragma unroll
        for (int ky = 0; ky < 5; ky++) {
            int j = r - ky;
            if (j >= 0 && j < 8) {
                acc[j] = fma2(f[ky * 5 + 0], q0, acc[j]);
                acc[j] = fma2(f[ky * 5 + 1], p1, acc[j]);
                acc[j] = fma2(f[ky * 5 + 2], q2, acc[j]);
                acc[j] = fma2(f[ky * 5 + 3], p3, acc[j]);
                acc[j] = fma2(f[ky * 5 + 4], q4, acc[j]);
            }
        }
    }

    float* op = out + (size_t)bc * HW + (size_t)(ty0 + oy) * 256 + tx0 + x;
#pragma unroll
    for (int j = 0; j < 8; j++)
        *(u64*)(op + (size_t)j * 256) = acc[j];
}

// ---------------------------------------------------------------------------
extern "C" void kernel_launch(void* const* d_in, const int* in_sizes, int n_in,
                              void* d_out, int out_size)
{
    const float* x    = (const float*)d_in[0];   // [8, 32, 256, 256]
    const float* w    = (const float*)d_in[1];   // [32, 32]
    const float* bias = (const float*)d_in[2];   // [32]
    float* out = (float*)d_out;                  // [8, 32, 256, 256]

    pool_kernel<<<dim3(NBC, 4), 256>>>(x);
    mix_kernel<<<dim3(128, NB), 256>>>(x, w, bias);
    filt_kernel<<<NB, 800>>>(w, bias);
    conv_kernel<<<dim3(16, NBC), 256>>>(out);
}

// round 6
// speedup vs baseline: 1.6511x; 1.6511x over previous
#include <cuda_runtime.h>
#include <cstdint>

typedef unsigned long long u64;

#define HW 65536           // 256*256
#define NB 8
#define NC 32
#define NBC 256

__device__ __align__(16) float g_feat[NB * NC * HW];
__device__ float g_pp[NBC * 4 * 25];
__device__ float g_filt[NBC * 25];

__device__ __forceinline__ u64 fma2(u64 a, u64 b, u64 c) {
    u64 d;
    asm("fma.rn.f32x2 %0, %1, %2, %3;" : "=l"(d) : "l"(a), "l"(b), "l"(c));
    return d;
}
__device__ __forceinline__ u64 dup(float f) {
    unsigned u = __float_as_uint(f);
    return ((u64)u << 32) | (u64)u;
}
__device__ __forceinline__ u64 packf(float lo, float hi) {
    u64 d;
    asm("mov.b64 %0, {%1, %2};" : "=l"(d) : "r"(__float_as_uint(lo)), "r"(__float_as_uint(hi)));
    return d;
}

// ---------------------------------------------------------------------------
// Kernel 1: channel mix (1x1 conv), occupancy-first fma2 version.
// Thread = 4 consecutive pixels (2 f32x2 pairs) x 8 out-channels
// -> only 16 u64 accumulators (~65 regs), 3 blocks/SM (37.5% occ).
// og = tid>>6 so all lanes of a warp share og: weight LDS are broadcasts.
// Per i-step: 1 LDG.128 (coalesced 512B/warp) + 4 LDS.128 + 16 fma2.
// grid = (256, 8), block = 256
// ---------------------------------------------------------------------------
__global__ __launch_bounds__(256, 3) void mix_kernel(
    const float* __restrict__ x,
    const float* __restrict__ w,
    const float* __restrict__ bias)
{
    __shared__ u64 wq[32 * 32];     // [i][o] duplicated, transposed
    __shared__ u64 b2[32];

    int tid = threadIdx.x;
    for (int idx = tid; idx < 1024; idx += 256) {
        int i = idx >> 5, o = idx & 31;
        wq[i * 32 + o] = dup(w[o * 32 + i]);
    }
    if (tid < 32)
        b2[tid] = dup(bias[tid]);
    __syncthreads();

    int og  = tid >> 6;        // out-channel group: channels og*8 .. og*8+7
    int t64 = tid & 63;        // pixel quad within the 256-px chunk

    size_t base = (size_t)blockIdx.y * (NC * HW) + blockIdx.x * 256 + t64 * 4;
    const float4* xp = (const float4*)(x + base);

    u64 acc[16];               // acc[k*2+p], k = och, p = pair
#pragma unroll
    for (int k = 0; k < 8; k++) {
        u64 bv = b2[og * 8 + k];
        acc[k * 2] = bv;
        acc[k * 2 + 1] = bv;
    }

#pragma unroll 4
    for (int i = 0; i < 32; i++) {
        float4 v = xp[(size_t)i * (HW / 4)];
        u64 x0 = packf(v.x, v.y);
        u64 x1 = packf(v.z, v.w);
        const ulonglong2* wr = (const ulonglong2*)(wq + i * 32 + og * 8);
#pragma unroll
        for (int k = 0; k < 4; k++) {
            ulonglong2 wp = wr[k];
            acc[(k * 2) * 2]         = fma2(wp.x, x0, acc[(k * 2) * 2]);
            acc[(k * 2) * 2 + 1]     = fma2(wp.x, x1, acc[(k * 2) * 2 + 1]);
            acc[(k * 2 + 1) * 2]     = fma2(wp.y, x0, acc[(k * 2 + 1) * 2]);
            acc[(k * 2 + 1) * 2 + 1] = fma2(wp.y, x1, acc[(k * 2 + 1) * 2 + 1]);
        }
    }

    float* fb = g_feat + base;
#pragma unroll
    for (int k = 0; k < 8; k++)
        *(ulonglong2*)(fb + (size_t)(og * 8 + k) * HW) =
            make_ulonglong2(acc[k * 2], acc[k * 2 + 1]);
}

// ---------------------------------------------------------------------------
// Kernel 2: adaptive pool partials on x (pooling commutes with the 1x1 conv).
// Row bins [0,52)[51,103)[102,154)[153,205)[204,256) (overlapping).
// grid = (256, 4 row-chunks), block = 256 (thread = column)
// ---------------------------------------------------------------------------
__global__ __launch_bounds__(256) void pool_kernel(const float* __restrict__ x)
{
    __shared__ float pool[25];
    int bc = blockIdx.x;
    int q  = blockIdx.y;
    int w  = threadIdx.x;
    if (w < 25) pool[w] = 0.0f;
    __syncthreads();

    const float* img = x + (size_t)bc * HW + (size_t)q * 64 * 256;

    float cs[5] = {0.f, 0.f, 0.f, 0.f, 0.f};
#pragma unroll
    for (int r = 0; r < 64; r++) {
        int h = q * 64 + r;
        float v = img[r * 256 + w];
        if (h < 52)              cs[0] += v;
        if (h >= 51 && h < 103)  cs[1] += v;
        if (h >= 102 && h < 154) cs[2] += v;
        if (h >= 153 && h < 205) cs[3] += v;
        if (h >= 204)            cs[4] += v;
    }

#pragma unroll
    for (int l = 0; l < 5; l++) {
        int s = (l * 256) / 5;
        int e = ((l + 1) * 256 + 4) / 5;
        if (w >= s && w < e) {
#pragma unroll
            for (int k = 0; k < 5; k++)
                if (cs[k] != 0.0f)
                    atomicAdd(&pool[k * 5 + l], cs[k]);
        }
    }
    __syncthreads();
    if (w < 25)
        g_pp[(bc * 4 + q) * 25 + w] = pool[w];
}

// ---------------------------------------------------------------------------
// Kernel 3: filt[b,o,kl] = bias[o] + sum_i w[o,i] * px[b,i,kl]
// grid = 8, block = 800
// ---------------------------------------------------------------------------
__global__ void filt_kernel(const float* __restrict__ w,
                            const float* __restrict__ bias)
{
    __shared__ float spx[800];
    int b = blockIdx.x;
    int t = threadIdx.x;
    int i  = t / 25;
    int kl = t - i * 25;

    float s = 0.0f;
#pragma unroll
    for (int q = 0; q < 4; q++)
        s += g_pp[((b * 32 + i) * 4 + q) * 25 + kl];
    spx[t] = s * (1.0f / 2704.0f);
    __syncthreads();

    float acc = bias[i];
#pragma unroll
    for (int ic = 0; ic < 32; ic++)
        acc += w[i * 32 + ic] * spx[ic * 25 + kl];
    g_filt[b * 800 + t] = acc;
}

// ---------------------------------------------------------------------------
// Kernel 4: depthwise 5x5 'same' conv — occupancy-first scalar version
// (best measured variant). 64x32 output tile, 36x68 halo in SMEM (9.8 KB),
// thread = 1 col x 8 rows; r-outer sliding window: each input value loaded
// once (60 LDS.32) feeding 200 scalar FFMAs. ~45 regs -> 5-6 blocks/SM.
// grid = (32, 256), block = 256
// ---------------------------------------------------------------------------
__global__ __launch_bounds__(256) void conv_kernel(float* __restrict__ out)
{
    __shared__ float sh[36 * 68];

    int bc  = blockIdx.y;
    int tile = blockIdx.x;
    int tx0 = (tile & 3) * 64;
    int ty0 = (tile >> 2) * 32;

    const float* img = g_feat + (size_t)bc * HW;

    float f[25];
#pragma unroll
    for (int t = 0; t < 25; t++) f[t] = g_filt[bc * 25 + t];

    for (int idx = threadIdx.x; idx < 36 * 68; idx += 256) {
        int r = idx / 68;
        int c = idx - r * 68;
        int gy = ty0 + r - 2;
        int gx = tx0 + c - 2;
        float v = 0.0f;
        if ((unsigned)gy < 256u && (unsigned)gx < 256u)
            v = img[gy * 256 + gx];
        sh[idx] = v;
    }
    __syncthreads();

    int x  = threadIdx.x & 63;
    int ys = (threadIdx.x >> 6) * 8;

    float acc[8];
#pragma unroll
    for (int j = 0; j < 8; j++) acc[j] = 0.0f;

#pragma unroll
    for (int r = 0; r < 12; r++) {
        const float* row = sh + (ys + r) * 68 + x;
        float v0 = row[0];
        float v1 = row[1];
        float v2 = row[2];
        float v3 = row[3];
        float v4 = row[4];
#pragma unroll
        for (int ky = 0; ky < 5; ky++) {
            int j = r - ky;
            if (j >= 0 && j < 8) {
                acc[j] += v0 * f[ky * 5 + 0];
                acc[j] += v1 * f[ky * 5 + 1];
                acc[j] += v2 * f[ky * 5 + 2];
                acc[j] += v3 * f[ky * 5 + 3];
                acc[j] += v4 * f[ky * 5 + 4];
            }
        }
    }

    float* op = out + (size_t)bc * HW + (size_t)(ty0 + ys) * 256 + tx0 + x;
#pragma unroll
    for (int j = 0; j < 8; j++)
        op[j * 256] = acc[j];
}

// ---------------------------------------------------------------------------
extern "C" void kernel_launch(void* const* d_in, const int* in_sizes, int n_in,
                              void* d_out, int out_size)
{
    const float* x    = (const float*)d_in[0];   // [8, 32, 256, 256]
    const float* w    = (const float*)d_in[1];   // [32, 32]
    const float* bias = (const float*)d_in[2];   // [32]
    float* out = (float*)d_out;                  // [8, 32, 256, 256]

    mix_kernel<<<dim3(256, NB), 256>>>(x, w, bias);
    pool_kernel<<<dim3(NBC, 4), 256>>>(x);
    filt_kernel<<<NB, 800>>>(w, bias);
    conv_kernel<<<dim3(32, NBC), 256>>>(out);
}

// round 7
// speedup vs baseline: 1.8360x; 1.1120x over previous
#include <cuda_runtime.h>
#include <cstdint>

typedef unsigned long long u64;

#define HW 65536           // 256*256
#define NB 8
#define NC 32
#define NBC 256

__device__ __align__(16) float g_feat[NB * NC * HW];
__device__ float g_pp[NBC * 4 * 25];
__device__ float g_filt[NBC * 25];

__device__ __forceinline__ u64 fma2(u64 a, u64 b, u64 c) {
    u64 d;
    asm("fma.rn.f32x2 %0, %1, %2, %3;" : "=l"(d) : "l"(a), "l"(b), "l"(c));
    return d;
}
__device__ __forceinline__ u64 dup(float f) {
    unsigned u = __float_as_uint(f);
    return ((u64)u << 32) | (u64)u;
}

// ---------------------------------------------------------------------------
// Kernel 1: channel mix (1x1 conv), latency-hiding-first.
// Warp = 16 out-channels x 64 px (1 f32x2 pair per lane): 16 u64 accs.
// Block = 8 warps = 2 och-groups x 4 px-segs = 256 px x 32 och.
// Per i-step: 1 LDG.64 (coalesced 256B/warp) + 8 LDS.128 (broadcast) +
// 16 fma2. ~60 regs, no reg cap -> 4 blocks/SM (8 warps/SMSP) hides the
// 577-cyc DRAM latency (8 x 104 cyc issue per unroll-4 window).
// grid = (256, 8), block = 256
// ---------------------------------------------------------------------------
__global__ __launch_bounds__(256) void mix_kernel(
    const float* __restrict__ x,
    const float* __restrict__ w,
    const float* __restrict__ bias)
{
    __shared__ u64 wq[32 * 32];     // [i][o] duplicated, transposed
    __shared__ u64 b2[32];

    int tid = threadIdx.x;
    for (int idx = tid; idx < 1024; idx += 256) {
        int i = idx >> 5, o = idx & 31;
        wq[i * 32 + o] = dup(w[o * 32 + i]);
    }
    if (tid < 32)
        b2[tid] = dup(bias[tid]);
    __syncthreads();

    int wid  = tid >> 5;
    int lane = tid & 31;
    int g = wid & 1;               // och group: channels g*16 .. g*16+15
    int s = wid >> 1;              // px segment (64 px each)

    int b = blockIdx.y;
    size_t pixpair = (size_t)blockIdx.x * 128 + s * 32 + lane;  // u64 index
    const u64* xp = (const u64*)x + (size_t)b * (NC * (HW / 2)) + pixpair;

    u64 acc[16];
#pragma unroll
    for (int k = 0; k < 16; k++) acc[k] = b2[g * 16 + k];

#pragma unroll 4
    for (int i = 0; i < 32; i++) {
        u64 xv = xp[(size_t)i * (HW / 2)];
        const ulonglong2* wr = (const ulonglong2*)(wq + i * 32 + g * 16);
#pragma unroll
        for (int k = 0; k < 8; k++) {
            ulonglong2 wp = wr[k];
            acc[2 * k]     = fma2(wp.x, xv, acc[2 * k]);
            acc[2 * k + 1] = fma2(wp.y, xv, acc[2 * k + 1]);
        }
    }

    u64* fb = (u64*)g_feat + (size_t)b * (NC * (HW / 2)) + pixpair;
#pragma unroll
    for (int k = 0; k < 16; k++)
        fb[(size_t)(g * 16 + k) * (HW / 2)] = acc[k];
}

// ---------------------------------------------------------------------------
// Kernel 2: adaptive pool partials on x (pooling commutes with the 1x1 conv).
// Row bins [0,52)[51,103)[102,154)[153,205)[204,256) (overlapping).
// grid = (256, 4 row-chunks), block = 256 (thread = column)
// ---------------------------------------------------------------------------
__global__ __launch_bounds__(256) void pool_kernel(const float* __restrict__ x)
{
    __shared__ float pool[25];
    int bc = blockIdx.x;
    int q  = blockIdx.y;
    int w  = threadIdx.x;
    if (w < 25) pool[w] = 0.0f;
    __syncthreads();

    const float* img = x + (size_t)bc * HW + (size_t)q * 64 * 256;

    float cs[5] = {0.f, 0.f, 0.f, 0.f, 0.f};
#pragma unroll
    for (int r = 0; r < 64; r++) {
        int h = q * 64 + r;
        float v = img[r * 256 + w];
        if (h < 52)              cs[0] += v;
        if (h >= 51 && h < 103)  cs[1] += v;
        if (h >= 102 && h < 154) cs[2] += v;
        if (h >= 153 && h < 205) cs[3] += v;
        if (h >= 204)            cs[4] += v;
    }

#pragma unroll
    for (int l = 0; l < 5; l++) {
        int s = (l * 256) / 5;
        int e = ((l + 1) * 256 + 4) / 5;
        if (w >= s && w < e) {
#pragma unroll
            for (int k = 0; k < 5; k++)
                if (cs[k] != 0.0f)
                    atomicAdd(&pool[k * 5 + l], cs[k]);
        }
    }
    __syncthreads();
    if (w < 25)
        g_pp[(bc * 4 + q) * 25 + w] = pool[w];
}

// ---------------------------------------------------------------------------
// Kernel 3: filt[b,o,kl] = bias[o] + sum_i w[o,i] * px[b,i,kl]
// grid = 8, block = 800
// ---------------------------------------------------------------------------
__global__ void filt_kernel(const float* __restrict__ w,
                            const float* __restrict__ bias)
{
    __shared__ float spx[800];
    int b = blockIdx.x;
    int t = threadIdx.x;
    int i  = t / 25;
    int kl = t - i * 25;

    float s = 0.0f;
#pragma unroll
    for (int q = 0; q < 4; q++)
        s += g_pp[((b * 32 + i) * 4 + q) * 25 + kl];
    spx[t] = s * (1.0f / 2704.0f);
    __syncthreads();

    float acc = bias[i];
#pragma unroll
    for (int ic = 0; ic < 32; ic++)
        acc += w[i * 32 + ic] * spx[ic * 25 + kl];
    g_filt[b * 800 + t] = acc;
}

// ---------------------------------------------------------------------------
// Kernel 4: depthwise 5x5 'same' conv — occupancy-first scalar version.
// 64x32 output tile, 36x68 halo in SMEM; thread = 1 col x 8 rows; r-outer
// sliding window (60 LDS.32 feeding 200 FFMAs). Halo staged via division-
// free 2D decomposition (9 strided row loads + 1 predicated edge load).
// grid = (32, 256), block = 256
// ---------------------------------------------------------------------------
__global__ __launch_bounds__(256) void conv_kernel(float* __restrict__ out)
{
    __shared__ float sh[36 * 68];

    int bc  = blockIdx.y;
    int tile = blockIdx.x;
    int tx0 = (tile & 3) * 64;
    int ty0 = (tile >> 2) * 32;

    const float* img = g_feat + (size_t)bc * HW;

    float f[25];
#pragma unroll
    for (int t = 0; t < 25; t++) f[t] = g_filt[bc * 25 + t];

    // halo staging: main 64 cols, 36 rows (thread = col x row-strided)
    {
        int c  = threadIdx.x & 63;
        int r0 = threadIdx.x >> 6;
        int gx = tx0 + c - 2;
        bool cin = (unsigned)gx < 256u;
#pragma unroll
        for (int k = 0; k < 9; k++) {
            int r = r0 + k * 4;
            int gy = ty0 + r - 2;
            float v = 0.0f;
            if (cin && (unsigned)gy < 256u)
                v = img[gy * 256 + gx];
            sh[r * 68 + c] = v;
        }
        // edge cols 64..67
        int c2 = 64 + (threadIdx.x & 3);
        int r2 = threadIdx.x >> 2;
        if (r2 < 36) {
            int gy = ty0 + r2 - 2;
            int gx2 = tx0 + c2 - 2;
            float v = 0.0f;
            if ((unsigned)gy < 256u && (unsigned)gx2 < 256u)
                v = img[gy * 256 + gx2];
            sh[r2 * 68 + c2] = v;
        }
    }
    __syncthreads();

    int x  = threadIdx.x & 63;
    int ys = (threadIdx.x >> 6) * 8;

    float acc[8];
#pragma unroll
    for (int j = 0; j < 8; j++) acc[j] = 0.0f;

#pragma unroll
    for (int r = 0; r < 12; r++) {
        const float* row = sh + (ys + r) * 68 + x;
        float v0 = row[0];
        float v1 = row[1];
        float v2 = row[2];
        float v3 = row[3];
        float v4 = row[4];
#pragma unroll
        for (int ky = 0; ky < 5; ky++) {
            int j = r - ky;
            if (j >= 0 && j < 8) {
                acc[j] += v0 * f[ky * 5 + 0];
                acc[j] += v1 * f[ky * 5 + 1];
                acc[j] += v2 * f[ky * 5 + 2];
                acc[j] += v3 * f[ky * 5 + 3];
                acc[j] += v4 * f[ky * 5 + 4];
            }
        }
    }

    float* op = out + (size_t)bc * HW + (size_t)(ty0 + ys) * 256 + tx0 + x;
#pragma unroll
    for (int j = 0; j < 8; j++)
        op[j * 256] = acc[j];
}

// ---------------------------------------------------------------------------
extern "C" void kernel_launch(void* const* d_in, const int* in_sizes, int n_in,
                              void* d_out, int out_size)
{
    const float* x    = (const float*)d_in[0];   // [8, 32, 256, 256]
    const float* w    = (const float*)d_in[1];   // [32, 32]
    const float* bias = (const float*)d_in[2];   // [32]
    float* out = (float*)d_out;                  // [8, 32, 256, 256]

    mix_kernel<<<dim3(256, NB), 256>>>(x, w, bias);
    pool_kernel<<<dim3(NBC, 4), 256>>>(x);
    filt_kernel<<<NB, 800>>>(w, bias);
    conv_kernel<<<dim3(32, NBC), 256>>>(out);
}

// round 8
// speedup vs baseline: 2.0225x; 1.1016x over previous
#include <cuda_runtime.h>
#include <cstdint>

#define HW 65536           // 256*256
#define NB 8
#define NC 32
#define NBC 256

__device__ __align__(16) float g_feat[NB * NC * HW];
__device__ float g_pp[NBC * 4 * 25];
__device__ float g_filt[NBC * 25];

// ---------------------------------------------------------------------------
// Kernel 1: channel mix (1x1 conv), SCALAR FFMA version.
// Warp = 16 out-channels x 64 px (1 float2 per lane -> 32 scalar accs).
// Block = 8 warps = 2 och-groups x 4 px-segments = 256 px x 32 och.
// Per i-step: 1 LDG.64 (coalesced 256B/warp) + 4 LDS.128 (weights,
// broadcast) + 32 scalar FFMA. ~60 regs -> 4 blocks/SM (8 warps/SMSP).
// grid = (256, 8), block = 256
// ---------------------------------------------------------------------------
__global__ __launch_bounds__(256) void mix_kernel(
    const float* __restrict__ x,
    const float* __restrict__ w,
    const float* __restrict__ bias)
{
    __shared__ float ws[32 * 32];   // [i][o] transposed
    __shared__ float bs[32];

    int tid = threadIdx.x;
    for (int idx = tid; idx < 1024; idx += 256) {
        int i = idx >> 5, o = idx & 31;
        ws[i * 32 + o] = w[o * 32 + i];
    }
    if (tid < 32)
        bs[tid] = bias[tid];
    __syncthreads();

    int wid  = tid >> 5;
    int lane = tid & 31;
    int g = wid & 1;               // och group: channels g*16 .. g*16+15
    int s = wid >> 1;              // px segment (64 px each)

    int b = blockIdx.y;
    size_t pixpair = (size_t)blockIdx.x * 128 + s * 32 + lane;  // float2 idx
    const float2* xp = (const float2*)x + (size_t)b * (NC * (HW / 2)) + pixpair;

    float ax[16], ay[16];
#pragma unroll
    for (int k = 0; k < 16; k++) {
        float bv = bs[g * 16 + k];
        ax[k] = bv;
        ay[k] = bv;
    }

#pragma unroll 8
    for (int i = 0; i < 32; i++) {
        float2 xv = xp[(size_t)i * (HW / 2)];
        const float4* wr = (const float4*)(ws + i * 32 + g * 16);
        float4 w0 = wr[0], w1 = wr[1], w2 = wr[2], w3 = wr[3];
        float wv[16] = {w0.x, w0.y, w0.z, w0.w, w1.x, w1.y, w1.z, w1.w,
                        w2.x, w2.y, w2.z, w2.w, w3.x, w3.y, w3.z, w3.w};
#pragma unroll
        for (int k = 0; k < 16; k++) {
            ax[k] = fmaf(wv[k], xv.x, ax[k]);
            ay[k] = fmaf(wv[k], xv.y, ay[k]);
        }
    }

    float2* fb = (float2*)g_feat + (size_t)b * (NC * (HW / 2)) + pixpair;
#pragma unroll
    for (int k = 0; k < 16; k++)
        fb[(size_t)(g * 16 + k) * (HW / 2)] = make_float2(ax[k], ay[k]);
}

// ---------------------------------------------------------------------------
// Kernel 2: adaptive pool partials on x (pooling commutes with the 1x1 conv).
// Row bins [0,52)[51,103)[102,154)[153,205)[204,256) (overlapping).
// grid = (256, 4 row-chunks), block = 256 (thread = column)
// ---------------------------------------------------------------------------
__global__ __launch_bounds__(256) void pool_kernel(const float* __restrict__ x)
{
    __shared__ float pool[25];
    int bc = blockIdx.x;
    int q  = blockIdx.y;
    int w  = threadIdx.x;
    if (w < 25) pool[w] = 0.0f;
    __syncthreads();

    const float* img = x + (size_t)bc * HW + (size_t)q * 64 * 256;

    float cs[5] = {0.f, 0.f, 0.f, 0.f, 0.f};
#pragma unroll
    for (int r = 0; r < 64; r++) {
        int h = q * 64 + r;
        float v = img[r * 256 + w];
        if (h < 52)              cs[0] += v;
        if (h >= 51 && h < 103)  cs[1] += v;
        if (h >= 102 && h < 154) cs[2] += v;
        if (h >= 153 && h < 205) cs[3] += v;
        if (h >= 204)            cs[4] += v;
    }

#pragma unroll
    for (int l = 0; l < 5; l++) {
        int s = (l * 256) / 5;
        int e = ((l + 1) * 256 + 4) / 5;
        if (w >= s && w < e) {
#pragma unroll
            for (int k = 0; k < 5; k++)
                if (cs[k] != 0.0f)
                    atomicAdd(&pool[k * 5 + l], cs[k]);
        }
    }
    __syncthreads();
    if (w < 25)
        g_pp[(bc * 4 + q) * 25 + w] = pool[w];
}

// ---------------------------------------------------------------------------
// Kernel 3: filt[b,o,kl] = bias[o] + sum_i w[o,i] * px[b,i,kl]
// grid = 8, block = 800
// ---------------------------------------------------------------------------
__global__ void filt_kernel(const float* __restrict__ w,
                            const float* __restrict__ bias)
{
    __shared__ float spx[800];
    int b = blockIdx.x;
    int t = threadIdx.x;
    int i  = t / 25;
    int kl = t - i * 25;

    float s = 0.0f;
#pragma unroll
    for (int q = 0; q < 4; q++)
        s += g_pp[((b * 32 + i) * 4 + q) * 25 + kl];
    spx[t] = s * (1.0f / 2704.0f);
    __syncthreads();

    float acc = bias[i];
#pragma unroll
    for (int ic = 0; ic < 32; ic++)
        acc += w[i * 32 + ic] * spx[ic * 25 + kl];
    g_filt[b * 800 + t] = acc;
}

// ---------------------------------------------------------------------------
// Kernel 4: depthwise 5x5 'same' conv — occupancy-first scalar version
// (unchanged from R7: 38 us, occ 91%, issue 70%).
// grid = (32, 256), block = 256
// ---------------------------------------------------------------------------
__global__ __launch_bounds__(256) void conv_kernel(float* __restrict__ out)
{
    __shared__ float sh[36 * 68];

    int bc  = blockIdx.y;
    int tile = blockIdx.x;
    int tx0 = (tile & 3) * 64;
    int ty0 = (tile >> 2) * 32;

    const float* img = g_feat + (size_t)bc * HW;

    float f[25];
#pragma unroll
    for (int t = 0; t < 25; t++) f[t] = g_filt[bc * 25 + t];

    {
        int c  = threadIdx.x & 63;
        int r0 = threadIdx.x >> 6;
        int gx = tx0 + c - 2;
        bool cin = (unsigned)gx < 256u;
#pragma unroll
        for (int k = 0; k < 9; k++) {
            int r = r0 + k * 4;
            int gy = ty0 + r - 2;
            float v = 0.0f;
            if (cin && (unsigned)gy < 256u)
                v = img[gy * 256 + gx];
            sh[r * 68 + c] = v;
        }
        int c2 = 64 + (threadIdx.x & 3);
        int r2 = threadIdx.x >> 2;
        if (r2 < 36) {
            int gy = ty0 + r2 - 2;
            int gx2 = tx0 + c2 - 2;
            float v = 0.0f;
            if ((unsigned)gy < 256u && (unsigned)gx2 < 256u)
                v = img[gy * 256 + gx2];
            sh[r2 * 68 + c2] = v;
        }
    }
    __syncthreads();

    int x  = threadIdx.x & 63;
    int ys = (threadIdx.x >> 6) * 8;

    float acc[8];
#pragma unroll
    for (int j = 0; j < 8; j++) acc[j] = 0.0f;

#pragma unroll
    for (int r = 0; r < 12; r++) {
        const float* row = sh + (ys + r) * 68 + x;
        float v0 = row[0];
        float v1 = row[1];
        float v2 = row[2];
        float v3 = row[3];
        float v4 = row[4];
#pragma unroll
        for (int ky = 0; ky < 5; ky++) {
            int j = r - ky;
            if (j >= 0 && j < 8) {
                acc[j] += v0 * f[ky * 5 + 0];
                acc[j] += v1 * f[ky * 5 + 1];
                acc[j] += v2 * f[ky * 5 + 2];
                acc[j] += v3 * f[ky * 5 + 3];
                acc[j] += v4 * f[ky * 5 + 4];
            }
        }
    }

    float* op = out + (size_t)bc * HW + (size_t)(ty0 + ys) * 256 + tx0 + x;
#pragma unroll
    for (int j = 0; j < 8; j++)
        op[j * 256] = acc[j];
}

// ---------------------------------------------------------------------------
extern "C" void kernel_launch(void* const* d_in, const int* in_sizes, int n_in,
                              void* d_out, int out_size)
{
    const float* x    = (const float*)d_in[0];   // [8, 32, 256, 256]
    const float* w    = (const float*)d_in[1];   // [32, 32]
    const float* bias = (const float*)d_in[2];   // [32]
    float* out = (float*)d_out;                  // [8, 32, 256, 256]

    mix_kernel<<<dim3(256, NB), 256>>>(x, w, bias);
    pool_kernel<<<dim3(NBC, 4), 256>>>(x);
    filt_kernel<<<NB, 800>>>(w, bias);
    conv_kernel<<<dim3(32, NBC), 256>>>(out);
}

// round 9
// speedup vs baseline: 2.3282x; 1.1511x over previous
#include <cuda_runtime.h>
#include <cstdint>

#define HW 65536           // 256*256
#define NB 8
#define NC 32
#define NBC 256

#define MIX_BLOCKS 2048    // 256 px-chunks x 8 batches
#define POOL_BLOCKS 1024   // 256 (b,c) x 4 row-chunks

__device__ __align__(16) float g_feat[NB * NC * HW];
__device__ float g_pp[NBC * 4 * 25];
__device__ float g_filt[NBC * 25];

// ---------------------------------------------------------------------------
// Kernel 1: FUSED channel-mix + adaptive-pool-partials, block-specialized.
// Blocks [0, 2048): mix — warp = 16 och x 64 px, 1 LDG.64 + 4 LDS.128 +
//   32 scalar FFMA per i-step (FMA-pipe bound).
// Blocks [2048, 3072): pool partials on x (DRAM-bound) — these co-reside
//   with mix blocks, stream under mix's spare memory bandwidth, and
//   backfill the ragged final wave of mix blocks.
// grid = 3072, block = 256
// ---------------------------------------------------------------------------
__global__ __launch_bounds__(256) void mixpool_kernel(
    const float* __restrict__ x,
    const float* __restrict__ w,
    const float* __restrict__ bias)
{
    if (blockIdx.x < MIX_BLOCKS) {
        // ------------------------- mix path -------------------------
        __shared__ float ws[32 * 32];   // [i][o] transposed
        __shared__ float bs[32];

        int tid = threadIdx.x;
        for (int idx = tid; idx < 1024; idx += 256) {
            int i = idx >> 5, o = idx & 31;
            ws[i * 32 + o] = w[o * 32 + i];
        }
        if (tid < 32)
            bs[tid] = bias[tid];
        __syncthreads();

        int wid  = tid >> 5;
        int lane = tid & 31;
        int g = wid & 1;               // och group: g*16 .. g*16+15
        int s = wid >> 1;              // px segment (64 px each)

        int b  = blockIdx.x >> 8;      // batch
        int cx = blockIdx.x & 255;     // 256-px chunk within image
        size_t pixpair = (size_t)cx * 128 + s * 32 + lane;   // float2 idx
        const float2* xp = (const float2*)x
                         + (size_t)b * (NC * (HW / 2)) + pixpair;

        float ax[16], ay[16];
#pragma unroll
        for (int k = 0; k < 16; k++) {
            float bv = bs[g * 16 + k];
            ax[k] = bv;
            ay[k] = bv;
        }

#pragma unroll 8
        for (int i = 0; i < 32; i++) {
            float2 xv = xp[(size_t)i * (HW / 2)];
            const float4* wr = (const float4*)(ws + i * 32 + g * 16);
            float4 w0 = wr[0], w1 = wr[1], w2 = wr[2], w3 = wr[3];
            float wv[16] = {w0.x, w0.y, w0.z, w0.w, w1.x, w1.y, w1.z, w1.w,
                            w2.x, w2.y, w2.z, w2.w, w3.x, w3.y, w3.z, w3.w};
#pragma unroll
            for (int k = 0; k < 16; k++) {
                ax[k] = fmaf(wv[k], xv.x, ax[k]);
                ay[k] = fmaf(wv[k], xv.y, ay[k]);
            }
        }

        float2* fb = (float2*)g_feat + (size_t)b * (NC * (HW / 2)) + pixpair;
#pragma unroll
        for (int k = 0; k < 16; k++)
            fb[(size_t)(g * 16 + k) * (HW / 2)] = make_float2(ax[k], ay[k]);

    } else {
        // ------------------------- pool path -------------------------
        // Row bins [0,52)[51,103)[102,154)[153,205)[204,256) (overlap).
        __shared__ float pool[25];
        int idx = blockIdx.x - MIX_BLOCKS;
        int bc = idx >> 2;             // (b*32 + channel)
        int q  = idx & 3;              // 64-row chunk
        int w_ = threadIdx.x;          // column
        if (w_ < 25) pool[w_] = 0.0f;
        __syncthreads();

        const float* img = x + (size_t)bc * HW + (size_t)q * 64 * 256;

        float cs[5] = {0.f, 0.f, 0.f, 0.f, 0.f};
#pragma unroll
        for (int r = 0; r < 64; r++) {
            int h = q * 64 + r;
            float v = img[r * 256 + w_];
            if (h < 52)              cs[0] += v;
            if (h >= 51 && h < 103)  cs[1] += v;
            if (h >= 102 && h < 154) cs[2] += v;
            if (h >= 153 && h < 205) cs[3] += v;
            if (h >= 204)            cs[4] += v;
        }

#pragma unroll
        for (int l = 0; l < 5; l++) {
            int s0 = (l * 256) / 5;
            int e0 = ((l + 1) * 256 + 4) / 5;
            if (w_ >= s0 && w_ < e0) {
#pragma unroll
                for (int k = 0; k < 5; k++)
                    if (cs[k] != 0.0f)
                        atomicAdd(&pool[k * 5 + l], cs[k]);
            }
        }
        __syncthreads();
        if (w_ < 25)
            g_pp[(bc * 4 + q) * 25 + w_] = pool[w_];
    }
}

// ---------------------------------------------------------------------------
// Kernel 2: filt[b,o,kl] = bias[o] + sum_i w[o,i] * px[b,i,kl]
// (pooling commutes with the 1x1 conv: pool matrix is row-stochastic)
// grid = 8, block = 800
// ---------------------------------------------------------------------------
__global__ void filt_kernel(const float* __restrict__ w,
                            const float* __restrict__ bias)
{
    __shared__ float spx[800];
    int b = blockIdx.x;
    int t = threadIdx.x;
    int i  = t / 25;
    int kl = t - i * 25;

    float s = 0.0f;
#pragma unroll
    for (int q = 0; q < 4; q++)
        s += g_pp[((b * 32 + i) * 4 + q) * 25 + kl];
    spx[t] = s * (1.0f / 2704.0f);
    __syncthreads();

    float acc = bias[i];
#pragma unroll
    for (int ic = 0; ic < 32; ic++)
        acc += w[i * 32 + ic] * spx[ic * 25 + kl];
    g_filt[b * 800 + t] = acc;
}

// ---------------------------------------------------------------------------
// Kernel 3: depthwise 5x5 'same' conv — occupancy-first scalar version
// (measured 38 us, occ 91%, issue 70%). 64x32 tile, 36x68 halo, thread =
// 1 col x 8 rows, division-free halo staging.
// grid = (32, 256), block = 256
// ---------------------------------------------------------------------------
__global__ __launch_bounds__(256) void conv_kernel(float* __restrict__ out)
{
    __shared__ float sh[36 * 68];

    int bc  = blockIdx.y;
    int tile = blockIdx.x;
    int tx0 = (tile & 3) * 64;
    int ty0 = (tile >> 2) * 32;

    const float* img = g_feat + (size_t)bc * HW;

    float f[25];
#pragma unroll
    for (int t = 0; t < 25; t++) f[t] = g_filt[bc * 25 + t];

    {
        int c  = threadIdx.x & 63;
        int r0 = threadIdx.x >> 6;
        int gx = tx0 + c - 2;
        bool cin = (unsigned)gx < 256u;
#pragma unroll
        for (int k = 0; k < 9; k++) {
            int r = r0 + k * 4;
            int gy = ty0 + r - 2;
            float v = 0.0f;
            if (cin && (unsigned)gy < 256u)
                v = img[gy * 256 + gx];
            sh[r * 68 + c] = v;
        }
        int c2 = 64 + (threadIdx.x & 3);
        int r2 = threadIdx.x >> 2;
        if (r2 < 36) {
            int gy = ty0 + r2 - 2;
            int gx2 = tx0 + c2 - 2;
            float v = 0.0f;
            if ((unsigned)gy < 256u && (unsigned)gx2 < 256u)
                v = img[gy * 256 + gx2];
            sh[r2 * 68 + c2] = v;
        }
    }
    __syncthreads();

    int x  = threadIdx.x & 63;
    int ys = (threadIdx.x >> 6) * 8;

    float acc[8];
#pragma unroll
    for (int j = 0; j < 8; j++) acc[j] = 0.0f;

#pragma unroll
    for (int r = 0; r < 12; r++) {
        const float* row = sh + (ys + r) * 68 + x;
        float v0 = row[0];
        float v1 = row[1];
        float v2 = row[2];
        float v3 = row[3];
        float v4 = row[4];
#pragma unroll
        for (int ky = 0; ky < 5; ky++) {
            int j = r - ky;
            if (j >= 0 && j < 8) {
                acc[j] += v0 * f[ky * 5 + 0];
                acc[j] += v1 * f[ky * 5 + 1];
                acc[j] += v2 * f[ky * 5 + 2];
                acc[j] += v3 * f[ky * 5 + 3];
                acc[j] += v4 * f[ky * 5 + 4];
            }
        }
    }

    float* op = out + (size_t)bc * HW + (size_t)(ty0 + ys) * 256 + tx0 + x;
#pragma unroll
    for (int j = 0; j < 8; j++)
        op[j * 256] = acc[j];
}

// ---------------------------------------------------------------------------
extern "C" void kernel_launch(void* const* d_in, const int* in_sizes, int n_in,
                              void* d_out, int out_size)
{
    const float* x    = (const float*)d_in[0];   // [8, 32, 256, 256]
    const float* w    = (const float*)d_in[1];   // [32, 32]
    const float* bias = (const float*)d_in[2];   // [32]
    float* out = (float*)d_out;                  // [8, 32, 256, 256]

    mixpool_kernel<<<MIX_BLOCKS + POOL_BLOCKS, 256>>>(x, w, bias);
    filt_kernel<<<NB, 800>>>(w, bias);
    conv_kernel<<<dim3(32, NBC), 256>>>(out);
}